// round 5
// baseline (speedup 1.0000x reference)
#include <cuda_runtime.h>
#include <cstdint>
#include <math.h>

#define D_MODEL 1024
#define NHEAD   16
#define HDIM    64
#define BATCH   2
#define SEQ     2048
#define MTOK    (BATCH * SEQ)   // 4096

// -------- scratch (static device globals; no allocation allowed) --------
// g_q/g_k/g_v hold tf32 BIT PATTERNS (stored as float), g_c holds fp32 ctx.
__device__ float g_q[MTOK * D_MODEL];
__device__ float g_k[MTOK * D_MODEL];
__device__ float g_v[MTOK * D_MODEL];
__device__ float g_c[MTOK * D_MODEL];

// ======================= helpers =======================
__device__ __forceinline__ uint32_t smem_u32(const void* p) {
    uint32_t a;
    asm("{ .reg .u64 t; cvta.to.shared.u64 t, %1; cvt.u32.u64 %0, t; }"
        : "=r"(a) : "l"(p));
    return a;
}

__device__ __forceinline__ unsigned f2tf(float x) {
    unsigned u;
    asm("cvt.rna.tf32.f32 %0, %1;" : "=r"(u) : "f"(x));
    return u;
}

__device__ __forceinline__ void mma8(float* d, unsigned a0, unsigned a1,
                                     unsigned a2, unsigned a3,
                                     unsigned b0, unsigned b1) {
    asm volatile(
        "mma.sync.aligned.m16n8k8.row.col.f32.tf32.tf32.f32 "
        "{%0,%1,%2,%3}, {%4,%5,%6,%7}, {%8,%9}, {%0,%1,%2,%3};"
        : "+f"(d[0]), "+f"(d[1]), "+f"(d[2]), "+f"(d[3])
        : "r"(a0), "r"(a1), "r"(a2), "r"(a3), "r"(b0), "r"(b1));
}

#define CP_A16(dst, src) \
    asm volatile("cp.async.ca.shared.global [%0], [%1], 16;" :: "r"(dst), "l"(src) : "memory")
#define CP_A4(dst, src) \
    asm volatile("cp.async.ca.shared.global [%0], [%1], 4;" :: "r"(dst), "l"(src) : "memory")
#define CP_COMMIT() asm volatile("cp.async.commit_group;" ::: "memory")
#define CP_WAIT(n)  asm volatile("cp.async.wait_group %0;" :: "n"(n) : "memory")

// ======================= GEMM:  Y = X @ W^T, cp.async 2-stage =======================
// X: (M,K) row-major fp32, W: (N,K) row-major fp32.
// outtf=0 -> fp32 (+bias). outtf=1 -> tf32 bit pattern of (scale*acc).
#define GST 36                       // smem row stride in floats (32 + 4 pad)
#define G_STAGE_B  (128 * GST * 4)   // 18432 bytes per operand per stage
#define G_AOFF(s)  ((s) * 2 * G_STAGE_B)
#define G_BOFF(s)  ((s) * 2 * G_STAGE_B + G_STAGE_B)
#define G_SMEM_BYTES (4 * G_STAGE_B) // 73728

__global__ __launch_bounds__(256, 2)
void gemm_cp(const float* __restrict__ X, const float* __restrict__ W,
             const float* __restrict__ bias, float* __restrict__ Y,
             int outtf, float scale)
{
    extern __shared__ char smem[];
    const uint32_t sb = smem_u32(smem);
    const int tid  = threadIdx.x;
    const int lane = tid & 31;
    const int wid  = tid >> 5;
    const int bm   = blockIdx.y * 128;
    const int bn   = blockIdx.x * 128;
    const int wm   = (wid & 3) * 32;
    const int wn   = (wid >> 2) * 64;
    const int g    = lane >> 2;
    const int t    = lane & 3;
    const int K    = D_MODEL;
    const int NSLAB = K / 32;        // 32

    // per-thread load coords (4 float4 per operand per slab)
    int lrow[4], lcg[4];
#pragma unroll
    for (int i = 0; i < 4; i++) {
        int f4 = tid + i * 256;
        lrow[i] = f4 >> 3;
        lcg[i]  = (f4 & 7) * 4;
    }

    auto issue = [&](int s, int k0) {
#pragma unroll
        for (int i = 0; i < 4; i++) {
            uint32_t doff = (uint32_t)(lrow[i] * GST + lcg[i]) * 4u;
            CP_A16(sb + G_AOFF(s) + doff, X + (size_t)(bm + lrow[i]) * K + k0 + lcg[i]);
            CP_A16(sb + G_BOFF(s) + doff, W + (size_t)(bn + lrow[i]) * K + k0 + lcg[i]);
        }
        CP_COMMIT();
    };

    float acc[2][8][4];
#pragma unroll
    for (int mt = 0; mt < 2; mt++)
#pragma unroll
        for (int nt = 0; nt < 8; nt++)
#pragma unroll
            for (int e = 0; e < 4; e++) acc[mt][nt][e] = 0.0f;

    issue(0, 0);

    for (int s = 0; s < NSLAB; s++) {
        const int buf = s & 1;
        if (s + 1 < NSLAB) { issue(buf ^ 1, (s + 1) * 32); CP_WAIT(1); }
        else               { CP_WAIT(0); }
        __syncthreads();

        const float* Af = (const float*)(smem + G_AOFF(buf));
        const float* Bf = (const float*)(smem + G_BOFF(buf));
#pragma unroll
        for (int k8 = 0; k8 < 4; k8++) {
            int kk = k8 * 8 + t;
            unsigned a[2][4];
#pragma unroll
            for (int mt = 0; mt < 2; mt++) {
                int r = wm + mt * 16 + g;
                a[mt][0] = f2tf(Af[r * GST + kk]);
                a[mt][1] = f2tf(Af[(r + 8) * GST + kk]);
                a[mt][2] = f2tf(Af[r * GST + kk + 4]);
                a[mt][3] = f2tf(Af[(r + 8) * GST + kk + 4]);
            }
#pragma unroll
            for (int nt = 0; nt < 8; nt++) {
                int c = wn + nt * 8 + g;
                unsigned b0 = f2tf(Bf[c * GST + kk]);
                unsigned b1 = f2tf(Bf[c * GST + kk + 4]);
                mma8(acc[0][nt], a[0][0], a[0][1], a[0][2], a[0][3], b0, b1);
                mma8(acc[1][nt], a[1][0], a[1][1], a[1][2], a[1][3], b0, b1);
            }
        }
        __syncthreads();   // all warps done with buf before it is re-filled
    }

#pragma unroll
    for (int mt = 0; mt < 2; mt++)
#pragma unroll
        for (int hh = 0; hh < 2; hh++) {
            int row = bm + wm + mt * 16 + g + hh * 8;
#pragma unroll
            for (int nt = 0; nt < 8; nt++) {
                int col = bn + wn + nt * 8 + t * 2;
                float x = acc[mt][nt][hh * 2 + 0];
                float y = acc[mt][nt][hh * 2 + 1];
                float2 v;
                if (outtf) {
                    v.x = __uint_as_float(f2tf(x * scale));
                    v.y = __uint_as_float(f2tf(y * scale));
                } else {
                    v.x = x + (bias ? bias[col] : 0.0f);
                    v.y = y + (bias ? bias[col + 1] : 0.0f);
                }
                *(float2*)(Y + (size_t)row * D_MODEL + col) = v;
            }
        }
}

// ======================= Flash attention (tf32 mma, cp.async, shuffle-P) =======================
// Inputs g_q/g_k/g_v are tf32 bit patterns; Q pre-scaled by 1/sqrt(64).
// Block: 8 warps, 128 q rows; key tiles of 64, double-buffered.
#define AST 68
#define A_QS   0                           // 128*68 uint
#define A_KS(b) (8704 + (b) * 4352)        // 64*68 each
#define A_VS(b) (17408 + (b) * 4352)
#define A_MK(b) (26112 + (b) * 64)         // 64 ints each
#define ATT_SMEM_BYTES ((26112 + 128) * 4) // 104960

__global__ __launch_bounds__(256, 2)
void attn_tc(const float* __restrict__ Qb, const float* __restrict__ Kb,
             const float* __restrict__ Vb, const int* __restrict__ mask,
             float* __restrict__ ctx)
{
    extern __shared__ char smem[];
    const uint32_t sb = smem_u32(smem);
    unsigned* SM = (unsigned*)smem;

    const int tid  = threadIdx.x;
    const int lane = tid & 31;
    const int wid  = tid >> 5;
    const int g    = lane >> 2;
    const int t    = lane & 3;
    const int q0   = blockIdx.x * 128;
    const int hd   = blockIdx.y;
    const int b    = blockIdx.z;

    const float* Qg = Qb + (size_t)(b * SEQ) * D_MODEL + hd * HDIM;
    const float* Kg = Kb + (size_t)(b * SEQ) * D_MODEL + hd * HDIM;
    const float* Vg = Vb + (size_t)(b * SEQ) * D_MODEL + hd * HDIM;
    const int*   Mg = mask + b * SEQ;

    // per-thread K/V load coords: 64 rows x 64 floats = 1024 float4, 4 per thread
    int krow[4], kcg[4];
#pragma unroll
    for (int i = 0; i < 4; i++) {
        int f4 = tid + i * 256;
        krow[i] = f4 >> 4;
        kcg[i]  = (f4 & 15) * 4;
    }

    auto issue_tile = [&](int buf, int kb) {
#pragma unroll
        for (int i = 0; i < 4; i++) {
            uint32_t doff = (uint32_t)(krow[i] * AST + kcg[i]) * 4u;
            CP_A16(sb + A_KS(buf) * 4u + doff, Kg + (size_t)(kb + krow[i]) * D_MODEL + kcg[i]);
            CP_A16(sb + A_VS(buf) * 4u + doff, Vg + (size_t)(kb + krow[i]) * D_MODEL + kcg[i]);
        }
        if (tid < 64) CP_A4(sb + A_MK(buf) * 4u + tid * 4u, Mg + kb + tid);
        CP_COMMIT();
    };

    issue_tile(0, 0);

    // ---- Q tile -> smem (raw tf32 bits, no cvt) ----
#pragma unroll
    for (int i = 0; i < 8; i++) {
        int f4  = tid + i * 256;
        int row = f4 >> 4;
        int cg  = (f4 & 15) * 4;
        *(uint4*)&SM[A_QS + row * AST + cg] =
            *(const uint4*)(Qg + (size_t)(q0 + row) * D_MODEL + cg);
    }

    float oacc[8][4];
#pragma unroll
    for (int dt = 0; dt < 8; dt++)
#pragma unroll
        for (int e = 0; e < 4; e++) oacc[dt][e] = 0.0f;
    float mrun[2] = {-1e30f, -1e30f};
    float lrun[2] = {0.0f, 0.0f};

    const int r = wid * 16 + g;
    const unsigned FULL = 0xffffffffu;
    const int srcL0 = (lane & ~3) | (t >> 1);
    const int srcL1 = srcL0 + 2;
    const bool odd = (t & 1);

    const int NT = SEQ / 64;   // 32

    for (int ti = 0; ti < NT; ti++) {
        const int buf = ti & 1;
        if (ti + 1 < NT) { issue_tile(buf ^ 1, (ti + 1) * 64); CP_WAIT(1); }
        else             { CP_WAIT(0); }
        __syncthreads();

        const unsigned* Ku = SM + A_KS(buf);
        const unsigned* Vu = SM + A_VS(buf);
        const int*      Mk = (const int*)(SM + A_MK(buf));

        // ---- S = Q K^T (C-layout accum) ----
        float sacc[8][4];
#pragma unroll
        for (int nt = 0; nt < 8; nt++)
#pragma unroll
            for (int e = 0; e < 4; e++) sacc[nt][e] = 0.0f;

#pragma unroll
        for (int d8 = 0; d8 < 8; d8++) {
            int kk = d8 * 8 + t;
            unsigned a0 = SM[A_QS + r * AST + kk];
            unsigned a1 = SM[A_QS + (r + 8) * AST + kk];
            unsigned a2 = SM[A_QS + r * AST + kk + 4];
            unsigned a3 = SM[A_QS + (r + 8) * AST + kk + 4];
#pragma unroll
            for (int nt = 0; nt < 8; nt++) {
                unsigned b0 = Ku[(nt * 8 + g) * AST + kk];
                unsigned b1 = Ku[(nt * 8 + g) * AST + kk + 4];
                mma8(sacc[nt], a0, a1, a2, a3, b0, b1);
            }
        }

        // ---- pass 1: mask add (C-layout) + row max + corr ----
        float mx[2] = {-1e30f, -1e30f};
#pragma unroll
        for (int nt = 0; nt < 8; nt++) {
            float mk0 = Mk[nt * 8 + t * 2]     ? 0.0f : -1e30f;
            float mk1 = Mk[nt * 8 + t * 2 + 1] ? 0.0f : -1e30f;
            sacc[nt][0] += mk0; sacc[nt][1] += mk1;
            sacc[nt][2] += mk0; sacc[nt][3] += mk1;
            mx[0] = fmaxf(mx[0], fmaxf(sacc[nt][0], sacc[nt][1]));
            mx[1] = fmaxf(mx[1], fmaxf(sacc[nt][2], sacc[nt][3]));
        }
        float corr[2];
#pragma unroll
        for (int h2 = 0; h2 < 2; h2++) {
            mx[h2] = fmaxf(mx[h2], __shfl_xor_sync(FULL, mx[h2], 1));
            mx[h2] = fmaxf(mx[h2], __shfl_xor_sync(FULL, mx[h2], 2));
            float mn = fmaxf(mrun[h2], mx[h2]);
            corr[h2] = __expf(mrun[h2] - mn);
            mrun[h2] = mn;
        }
#pragma unroll
        for (int dt = 0; dt < 8; dt++) {
            oacc[dt][0] *= corr[0]; oacc[dt][1] *= corr[0];
            oacc[dt][2] *= corr[1]; oacc[dt][3] *= corr[1];
        }

        // ---- pass 2: per 8-col block: redistribute C->A layout, exp, PV mma ----
        float ls[2] = {0.0f, 0.0f};
#pragma unroll
        for (int j8 = 0; j8 < 8; j8++) {
            // row g: cols t (p0) and t+4 (p2)
            float v0 = __shfl_sync(FULL, sacc[j8][0], srcL0);
            float v1 = __shfl_sync(FULL, sacc[j8][1], srcL0);
            float w0 = __shfl_sync(FULL, sacc[j8][0], srcL1);
            float w1 = __shfl_sync(FULL, sacc[j8][1], srcL1);
            float p0 = odd ? v1 : v0;
            float p2 = odd ? w1 : w0;
            // row g+8
            float x0 = __shfl_sync(FULL, sacc[j8][2], srcL0);
            float x1 = __shfl_sync(FULL, sacc[j8][3], srcL0);
            float y0 = __shfl_sync(FULL, sacc[j8][2], srcL1);
            float y1 = __shfl_sync(FULL, sacc[j8][3], srcL1);
            float p1 = odd ? x1 : x0;
            float p3 = odd ? y1 : y0;

            p0 = __expf(p0 - mrun[0]);
            p2 = __expf(p2 - mrun[0]);
            p1 = __expf(p1 - mrun[1]);
            p3 = __expf(p3 - mrun[1]);
            ls[0] += p0 + p2;
            ls[1] += p1 + p3;

            unsigned ua0 = f2tf(p0), ua1 = f2tf(p1);
            unsigned ua2 = f2tf(p2), ua3 = f2tf(p3);
#pragma unroll
            for (int dt = 0; dt < 8; dt++) {
                unsigned b0 = Vu[(j8 * 8 + t) * AST + dt * 8 + g];
                unsigned b1 = Vu[(j8 * 8 + 4 + t) * AST + dt * 8 + g];
                mma8(oacc[dt], ua0, ua1, ua2, ua3, b0, b1);
            }
        }
#pragma unroll
        for (int h2 = 0; h2 < 2; h2++) {
            ls[h2] += __shfl_xor_sync(FULL, ls[h2], 1);
            ls[h2] += __shfl_xor_sync(FULL, ls[h2], 2);
            lrun[h2] = lrun[h2] * corr[h2] + ls[h2];
        }
        __syncthreads();   // all warps done with buf before refill
    }

    // ---- normalize + write ctx ----
    float inv[2];
    inv[0] = (mrun[0] > -9e29f) ? (1.0f / lrun[0]) : 0.0f;
    inv[1] = (mrun[1] > -9e29f) ? (1.0f / lrun[1]) : 0.0f;
#pragma unroll
    for (int h2 = 0; h2 < 2; h2++) {
        int row = q0 + r + h2 * 8;
        float* dst = ctx + (size_t)(b * SEQ + row) * D_MODEL + hd * HDIM;
#pragma unroll
        for (int dt = 0; dt < 8; dt++) {
            float2 v;
            v.x = oacc[dt][h2 * 2 + 0] * inv[h2];
            v.y = oacc[dt][h2 * 2 + 1] * inv[h2];
            *(float2*)(dst + dt * 8 + t * 2) = v;
        }
    }
}

// ======================= launch =======================
extern "C" void kernel_launch(void* const* d_in, const int* in_sizes, int n_in,
                              void* d_out, int out_size)
{
    const float* q   = (const float*)d_in[0];
    const float* k   = (const float*)d_in[1];
    const float* v   = (const float*)d_in[2];
    const int*   msk = (const int*)  d_in[3];
    const float* Wq  = (const float*)d_in[4];
    const float* Wk  = (const float*)d_in[5];
    const float* Wv  = (const float*)d_in[6];
    const float* Wo  = (const float*)d_in[7];
    const float* bo  = (const float*)d_in[8];
    float* out = (float*)d_out;

    float *gq, *gk, *gv, *gc;
    cudaGetSymbolAddress((void**)&gq, g_q);
    cudaGetSymbolAddress((void**)&gk, g_k);
    cudaGetSymbolAddress((void**)&gv, g_v);
    cudaGetSymbolAddress((void**)&gc, g_c);

    cudaFuncSetAttribute(gemm_cp,
                         cudaFuncAttributeMaxDynamicSharedMemorySize, G_SMEM_BYTES);
    cudaFuncSetAttribute(attn_tc,
                         cudaFuncAttributeMaxDynamicSharedMemorySize, ATT_SMEM_BYTES);

    dim3 gg(D_MODEL / 128, MTOK / 128);   // (8, 32)

    gemm_cp<<<gg, 256, G_SMEM_BYTES>>>(q, Wq, nullptr, gq, 1, 0.125f); // Q: tf32, pre-scaled
    gemm_cp<<<gg, 256, G_SMEM_BYTES>>>(k, Wk, nullptr, gk, 1, 1.0f);   // K: tf32
    gemm_cp<<<gg, 256, G_SMEM_BYTES>>>(v, Wv, nullptr, gv, 1, 1.0f);   // V: tf32

    dim3 ag(SEQ / 128, NHEAD, BATCH);     // (16, 16, 2)
    attn_tc<<<ag, 256, ATT_SMEM_BYTES>>>(gq, gk, gv, msk, gc);

    gemm_cp<<<gg, 256, G_SMEM_BYTES>>>(gc, Wo, bo, out, 0, 1.0f);      // O proj: fp32 + bias
}

// round 6
// speedup vs baseline: 2.0323x; 2.0323x over previous
#include <cuda_runtime.h>
#include <cuda_fp16.h>
#include <cstdint>
#include <math.h>

#define D_MODEL 1024
#define NHEAD   16
#define HDIM    64
#define BATCH   2
#define SEQ     2048
#define MTOK    (BATCH * SEQ)   // 4096

// -------- scratch (static device globals; no allocation allowed) --------
__device__ __half g_qh[MTOK * D_MODEL];   // fp16 Q (pre-scaled by 0.125)
__device__ __half g_kh[MTOK * D_MODEL];   // fp16 K
__device__ __half g_vh[MTOK * D_MODEL];   // fp16 V
__device__ float  g_c [MTOK * D_MODEL];   // fp32 ctx

// ======================= helpers =======================
__device__ __forceinline__ uint32_t smem_u32(const void* p) {
    uint32_t a;
    asm("{ .reg .u64 t; cvta.to.shared.u64 t, %1; cvt.u32.u64 %0, t; }"
        : "=r"(a) : "l"(p));
    return a;
}

__device__ __forceinline__ unsigned f2tf(float x) {
    unsigned u;
    asm("cvt.rna.tf32.f32 %0, %1;" : "=r"(u) : "f"(x));
    return u;
}

__device__ __forceinline__ void mma8(float* d, unsigned a0, unsigned a1,
                                     unsigned a2, unsigned a3,
                                     unsigned b0, unsigned b1) {
    asm volatile(
        "mma.sync.aligned.m16n8k8.row.col.f32.tf32.tf32.f32 "
        "{%0,%1,%2,%3}, {%4,%5,%6,%7}, {%8,%9}, {%0,%1,%2,%3};"
        : "+f"(d[0]), "+f"(d[1]), "+f"(d[2]), "+f"(d[3])
        : "r"(a0), "r"(a1), "r"(a2), "r"(a3), "r"(b0), "r"(b1));
}

__device__ __forceinline__ void mma16h(float* d, const unsigned* a,
                                       unsigned b0, unsigned b1) {
    asm volatile(
        "mma.sync.aligned.m16n8k16.row.col.f32.f16.f16.f32 "
        "{%0,%1,%2,%3}, {%4,%5,%6,%7}, {%8,%9}, {%0,%1,%2,%3};"
        : "+f"(d[0]), "+f"(d[1]), "+f"(d[2]), "+f"(d[3])
        : "r"(a[0]), "r"(a[1]), "r"(a[2]), "r"(a[3]), "r"(b0), "r"(b1));
}

__device__ __forceinline__ void ldsm4(unsigned* r, uint32_t a) {
    asm volatile("ldmatrix.sync.aligned.m8n8.x4.shared.b16 {%0,%1,%2,%3}, [%4];"
                 : "=r"(r[0]), "=r"(r[1]), "=r"(r[2]), "=r"(r[3]) : "r"(a));
}
__device__ __forceinline__ void ldsm4t(unsigned* r, uint32_t a) {
    asm volatile("ldmatrix.sync.aligned.m8n8.x4.trans.shared.b16 {%0,%1,%2,%3}, [%4];"
                 : "=r"(r[0]), "=r"(r[1]), "=r"(r[2]), "=r"(r[3]) : "r"(a));
}

#define CP_A16(dst, src) \
    asm volatile("cp.async.ca.shared.global [%0], [%1], 16;" :: "r"(dst), "l"(src) : "memory")
#define CP_A4(dst, src) \
    asm volatile("cp.async.ca.shared.global [%0], [%1], 4;" :: "r"(dst), "l"(src) : "memory")
#define CP_COMMIT() asm volatile("cp.async.commit_group;" ::: "memory")
#define CP_WAIT(n)  asm volatile("cp.async.wait_group %0;" :: "n"(n) : "memory")

// ======================= GEMM (R2 form):  Y = X @ W^T =======================
// X: (M,K) row-major fp32, W: (N,K) row-major fp32.
// outmode 0: fp32 + bias.  outmode 1: fp16 of (scale*acc).
#define BKG 32
#define KST 36   // smem row stride (floats)

__global__ __launch_bounds__(256, 2)
void gemm_tf32(const float* __restrict__ X, const float* __restrict__ W,
               const float* __restrict__ bias, void* __restrict__ Yv,
               int outmode, float scale)
{
    __shared__ unsigned As[128][KST];
    __shared__ unsigned Bs[128][KST];

    const int tid  = threadIdx.x;
    const int lane = tid & 31;
    const int wid  = tid >> 5;
    const int bm   = blockIdx.y * 128;
    const int bn   = blockIdx.x * 128;
    const int wm   = (wid & 3) * 32;
    const int wn   = (wid >> 2) * 64;
    const int g    = lane >> 2;
    const int t    = lane & 3;
    const int K    = D_MODEL;

    float acc[2][8][4];
#pragma unroll
    for (int mt = 0; mt < 2; mt++)
#pragma unroll
        for (int nt = 0; nt < 8; nt++)
#pragma unroll
            for (int e = 0; e < 4; e++) acc[mt][nt][e] = 0.0f;

    for (int k0 = 0; k0 < K; k0 += BKG) {
#pragma unroll
        for (int i = 0; i < 4; i++) {
            int f4  = tid + i * 256;
            int row = f4 >> 3;
            int cg  = (f4 & 7) * 4;
            float4 xv = *(const float4*)(X + (size_t)(bm + row) * K + k0 + cg);
            *(uint4*)&As[row][cg] =
                make_uint4(f2tf(xv.x), f2tf(xv.y), f2tf(xv.z), f2tf(xv.w));
            float4 wv = *(const float4*)(W + (size_t)(bn + row) * K + k0 + cg);
            *(uint4*)&Bs[row][cg] =
                make_uint4(f2tf(wv.x), f2tf(wv.y), f2tf(wv.z), f2tf(wv.w));
        }
        __syncthreads();

#pragma unroll
        for (int k8 = 0; k8 < 4; k8++) {
            int kk = k8 * 8 + t;
            unsigned a[2][4];
#pragma unroll
            for (int mt = 0; mt < 2; mt++) {
                int r = wm + mt * 16 + g;
                a[mt][0] = As[r][kk];
                a[mt][1] = As[r + 8][kk];
                a[mt][2] = As[r][kk + 4];
                a[mt][3] = As[r + 8][kk + 4];
            }
#pragma unroll
            for (int nt = 0; nt < 8; nt++) {
                int c = wn + nt * 8 + g;
                unsigned b0 = Bs[c][kk];
                unsigned b1 = Bs[c][kk + 4];
                mma8(acc[0][nt], a[0][0], a[0][1], a[0][2], a[0][3], b0, b1);
                mma8(acc[1][nt], a[1][0], a[1][1], a[1][2], a[1][3], b0, b1);
            }
        }
        __syncthreads();
    }

#pragma unroll
    for (int mt = 0; mt < 2; mt++)
#pragma unroll
        for (int hh = 0; hh < 2; hh++) {
            int row = bm + wm + mt * 16 + g + hh * 8;
#pragma unroll
            for (int nt = 0; nt < 8; nt++) {
                int col = bn + wn + nt * 8 + t * 2;
                float x = acc[mt][nt][hh * 2 + 0];
                float y = acc[mt][nt][hh * 2 + 1];
                if (outmode) {
                    __half2 h = __floats2half2_rn(x * scale, y * scale);
                    *(__half2*)((__half*)Yv + (size_t)row * D_MODEL + col) = h;
                } else {
                    float2 v;
                    v.x = x + (bias ? bias[col] : 0.0f);
                    v.y = y + (bias ? bias[col + 1] : 0.0f);
                    *(float2*)((float*)Yv + (size_t)row * D_MODEL + col) = v;
                }
            }
        }
}

// ======================= Flash attention: fp16 mma + ldmatrix =======================
// Q/K/V fp16 (Q pre-scaled). 8 warps, 128 q rows/CTA; 64-key tiles, cp.async 2-stage.
// smem halves stride 72 (144 B/row, 16B-aligned rows, conflict-free LDSM).
#define HSTB 144                      // row stride bytes (72 halves)
#define QS_B   0                      // 128 rows
#define KS_B(b) (18432 + (b) * 9216)  // 64 rows each
#define VS_B(b) (36864 + (b) * 9216)
#define PS_B   55296                  // 128 rows
#define MK_B(b) (73728 + (b) * 256)   // 64 ints each
#define ATT_SMEM_BYTES (74240)

__global__ __launch_bounds__(256, 2)
void attn_h(const __half* __restrict__ Qb, const __half* __restrict__ Kb,
            const __half* __restrict__ Vb, const int* __restrict__ mask,
            float* __restrict__ ctx)
{
    extern __shared__ char sm[];
    const uint32_t sb = smem_u32(sm);

    const int tid  = threadIdx.x;
    const int lane = tid & 31;
    const int wid  = tid >> 5;
    const int g    = lane >> 2;
    const int t    = lane & 3;
    const int q0   = blockIdx.x * 128;
    const int hd   = blockIdx.y;
    const int b    = blockIdx.z;

    const __half* Qg = Qb + (size_t)(b * SEQ) * D_MODEL + hd * HDIM;
    const __half* Kg = Kb + (size_t)(b * SEQ) * D_MODEL + hd * HDIM;
    const __half* Vg = Vb + (size_t)(b * SEQ) * D_MODEL + hd * HDIM;
    const int*    Mg = mask + b * SEQ;

    // K/V tile load coords: 64 rows x 8 16B-chunks = 512 chunks, 2/thread/operand
    int jr[2], jc[2];
#pragma unroll
    for (int i = 0; i < 2; i++) {
        int idx = tid + i * 256;
        jr[i] = idx >> 3;
        jc[i] = idx & 7;
    }

    auto issue_tile = [&](int buf, int kb) {
#pragma unroll
        for (int i = 0; i < 2; i++) {
            uint32_t doff = (uint32_t)(jr[i] * HSTB + jc[i] * 16);
            CP_A16(sb + KS_B(buf) + doff, Kg + (size_t)(kb + jr[i]) * D_MODEL + jc[i] * 8);
            CP_A16(sb + VS_B(buf) + doff, Vg + (size_t)(kb + jr[i]) * D_MODEL + jc[i] * 8);
        }
        if (tid < 64) CP_A4(sb + MK_B(buf) + tid * 4, Mg + kb + tid);
        CP_COMMIT();
    };

    issue_tile(0, 0);

    // ---- Q tile -> smem (raw fp16, pure copy) ----
#pragma unroll
    for (int i = 0; i < 4; i++) {
        int idx = tid + i * 256;        // 1024 chunks
        int row = idx >> 3;
        int c8  = idx & 7;
        *(uint4*)(sm + QS_B + row * HSTB + c8 * 16) =
            *(const uint4*)(Qg + (size_t)(q0 + row) * D_MODEL + c8 * 8);
    }

    // per-lane LDSM addresses
    const int l7  = lane & 7;
    const int lb3 = (lane >> 3) & 1;
    const int lb4 = lane >> 4;
    // A-frag (Q/P): row = wid*16 + l7 + (lane&8), col16B-block = lb4
    const uint32_t qa = sb + QS_B + (uint32_t)((wid * 16 + l7 + (lane & 8)) * HSTB) + lb4 * 16;
    const uint32_t pa = sb + PS_B + (uint32_t)((wid * 16 + l7 + (lane & 8)) * HSTB) + lb4 * 16;
    // K B-frag: row = np*16 + l7 + lb4*8, col = lb3*16B (+ s*32B)
    const uint32_t koff = (uint32_t)((l7 + lb4 * 8) * HSTB) + lb3 * 16;
    // V trans B-frag: row = s*16 + l7 + lb3*8, col = dp*16 + lb4*8 halves
    const uint32_t voff = (uint32_t)((l7 + lb3 * 8) * HSTB) + lb4 * 16;

    float oacc[8][4];
#pragma unroll
    for (int dt = 0; dt < 8; dt++)
#pragma unroll
        for (int e = 0; e < 4; e++) oacc[dt][e] = 0.0f;
    float mrun[2] = {-1e30f, -1e30f};
    float lrun[2] = {0.0f, 0.0f};

    const int r = wid * 16 + g;
    const unsigned FULL = 0xffffffffu;
    const int NT = SEQ / 64;   // 32

    for (int ti = 0; ti < NT; ti++) {
        const int buf = ti & 1;
        if (ti + 1 < NT) { issue_tile(buf ^ 1, (ti + 1) * 64); CP_WAIT(1); }
        else             { CP_WAIT(0); }
        __syncthreads();

        const uint32_t kbase = sb + KS_B(buf) + koff;
        const uint32_t vbase = sb + VS_B(buf) + voff;
        const int*     Mk    = (const int*)(sm + MK_B(buf));

        // ---- S = Q K^T ----
        float sacc[8][4];
#pragma unroll
        for (int nt = 0; nt < 8; nt++)
#pragma unroll
            for (int e = 0; e < 4; e++) sacc[nt][e] = 0.0f;

#pragma unroll
        for (int s = 0; s < 4; s++) {
            unsigned a[4];
            ldsm4(a, qa + s * 32);
#pragma unroll
            for (int np = 0; np < 4; np++) {
                unsigned kb4[4];
                ldsm4(kb4, kbase + np * 16 * HSTB + s * 32);
                mma16h(sacc[2 * np],     a, kb4[0], kb4[1]);
                mma16h(sacc[2 * np + 1], a, kb4[2], kb4[3]);
            }
        }

        // ---- mask + online softmax (C layout: rows g/g+8, cols nt*8+2t,+1) ----
        float mx[2] = {-1e30f, -1e30f};
#pragma unroll
        for (int nt = 0; nt < 8; nt++) {
            float mk0 = Mk[nt * 8 + t * 2]     ? 0.0f : -1e30f;
            float mk1 = Mk[nt * 8 + t * 2 + 1] ? 0.0f : -1e30f;
            sacc[nt][0] += mk0; sacc[nt][1] += mk1;
            sacc[nt][2] += mk0; sacc[nt][3] += mk1;
            mx[0] = fmaxf(mx[0], fmaxf(sacc[nt][0], sacc[nt][1]));
            mx[1] = fmaxf(mx[1], fmaxf(sacc[nt][2], sacc[nt][3]));
        }
        float corr[2];
#pragma unroll
        for (int h2 = 0; h2 < 2; h2++) {
            mx[h2] = fmaxf(mx[h2], __shfl_xor_sync(FULL, mx[h2], 1));
            mx[h2] = fmaxf(mx[h2], __shfl_xor_sync(FULL, mx[h2], 2));
            float mn = fmaxf(mrun[h2], mx[h2]);
            corr[h2] = __expf(mrun[h2] - mn);
            mrun[h2] = mn;
        }
        float ls[2] = {0.0f, 0.0f};
#pragma unroll
        for (int nt = 0; nt < 8; nt++) {
            sacc[nt][0] = __expf(sacc[nt][0] - mrun[0]);
            sacc[nt][1] = __expf(sacc[nt][1] - mrun[0]);
            sacc[nt][2] = __expf(sacc[nt][2] - mrun[1]);
            sacc[nt][3] = __expf(sacc[nt][3] - mrun[1]);
            ls[0] += sacc[nt][0] + sacc[nt][1];
            ls[1] += sacc[nt][2] + sacc[nt][3];
        }
#pragma unroll
        for (int h2 = 0; h2 < 2; h2++) {
            ls[h2] += __shfl_xor_sync(FULL, ls[h2], 1);
            ls[h2] += __shfl_xor_sync(FULL, ls[h2], 2);
            lrun[h2] = lrun[h2] * corr[h2] + ls[h2];
        }
#pragma unroll
        for (int dt = 0; dt < 8; dt++) {
            oacc[dt][0] *= corr[0]; oacc[dt][1] *= corr[0];
            oacc[dt][2] *= corr[1]; oacc[dt][3] *= corr[1];
        }

        // ---- P -> smem as fp16 (warp-private rows; no block barrier) ----
#pragma unroll
        for (int nt = 0; nt < 8; nt++) {
            int cb = (nt * 8 + t * 2) * 2;   // byte offset of col pair
            *(__half2*)(sm + PS_B + r * HSTB + cb) =
                __floats2half2_rn(sacc[nt][0], sacc[nt][1]);
            *(__half2*)(sm + PS_B + (r + 8) * HSTB + cb) =
                __floats2half2_rn(sacc[nt][2], sacc[nt][3]);
        }
        __syncwarp();

        // ---- O += P @ V (V via ldmatrix.trans, natural [j][d] layout) ----
#pragma unroll
        for (int s = 0; s < 4; s++) {
            unsigned p4[4];
            ldsm4(p4, pa + s * 32);
#pragma unroll
            for (int dp = 0; dp < 4; dp++) {
                unsigned vb4[4];
                ldsm4t(vb4, vbase + s * 16 * HSTB + dp * 32);
                mma16h(oacc[2 * dp],     p4, vb4[0], vb4[1]);
                mma16h(oacc[2 * dp + 1], p4, vb4[2], vb4[3]);
            }
        }
        __syncthreads();   // all warps done with buf before it is refilled
    }

    // ---- normalize + write ctx ----
    float inv[2];
    inv[0] = (mrun[0] > -9e29f) ? (1.0f / lrun[0]) : 0.0f;
    inv[1] = (mrun[1] > -9e29f) ? (1.0f / lrun[1]) : 0.0f;
#pragma unroll
    for (int h2 = 0; h2 < 2; h2++) {
        int row = q0 + r + h2 * 8;
        float* dst = ctx + (size_t)(b * SEQ + row) * D_MODEL + hd * HDIM;
#pragma unroll
        for (int dt = 0; dt < 8; dt++) {
            float2 v;
            v.x = oacc[dt][h2 * 2 + 0] * inv[h2];
            v.y = oacc[dt][h2 * 2 + 1] * inv[h2];
            *(float2*)(dst + dt * 8 + t * 2) = v;
        }
    }
}

// ======================= launch =======================
extern "C" void kernel_launch(void* const* d_in, const int* in_sizes, int n_in,
                              void* d_out, int out_size)
{
    const float* q   = (const float*)d_in[0];
    const float* k   = (const float*)d_in[1];
    const float* v   = (const float*)d_in[2];
    const int*   msk = (const int*)  d_in[3];
    const float* Wq  = (const float*)d_in[4];
    const float* Wk  = (const float*)d_in[5];
    const float* Wv  = (const float*)d_in[6];
    const float* Wo  = (const float*)d_in[7];
    const float* bo  = (const float*)d_in[8];
    float* out = (float*)d_out;

    __half *gq, *gk, *gv;
    float  *gc;
    cudaGetSymbolAddress((void**)&gq, g_qh);
    cudaGetSymbolAddress((void**)&gk, g_kh);
    cudaGetSymbolAddress((void**)&gv, g_vh);
    cudaGetSymbolAddress((void**)&gc, g_c);

    cudaFuncSetAttribute(attn_h,
                         cudaFuncAttributeMaxDynamicSharedMemorySize, ATT_SMEM_BYTES);

    dim3 gg(D_MODEL / 128, MTOK / 128);   // (8, 32)

    gemm_tf32<<<gg, 256>>>(q, Wq, nullptr, gq, 1, 0.125f);  // Q -> fp16, pre-scaled
    gemm_tf32<<<gg, 256>>>(k, Wk, nullptr, gk, 1, 1.0f);    // K -> fp16
    gemm_tf32<<<gg, 256>>>(v, Wv, nullptr, gv, 1, 1.0f);    // V -> fp16

    dim3 ag(SEQ / 128, NHEAD, BATCH);     // (16, 16, 2)
    attn_h<<<ag, 256, ATT_SMEM_BYTES>>>(gq, gk, gv, msk, gc);

    gemm_tf32<<<gg, 256>>>(gc, Wo, bo, out, 0, 1.0f);       // O proj fp32 + bias
}

// round 8
// speedup vs baseline: 2.5819x; 1.2704x over previous
#include <cuda_runtime.h>
#include <cuda_fp16.h>
#include <cstdint>
#include <math.h>

#define D_MODEL 1024
#define NHEAD   16
#define HDIM    64
#define BATCH   2
#define SEQ     2048
#define MTOK    (BATCH * SEQ)   // 4096

// -------- scratch (static device globals; no allocation allowed) --------
__device__ __half g_qh[MTOK * D_MODEL];   // fp16 Q (pre-scaled by 0.125)
__device__ __half g_kh[MTOK * D_MODEL];   // fp16 K
__device__ __half g_vh[MTOK * D_MODEL];   // fp16 V
__device__ float  g_c [MTOK * D_MODEL];   // fp32 ctx

// ======================= helpers =======================
__device__ __forceinline__ uint32_t smem_u32(const void* p) {
    uint32_t a;
    asm("{ .reg .u64 t; cvta.to.shared.u64 t, %1; cvt.u32.u64 %0, t; }"
        : "=r"(a) : "l"(p));
    return a;
}

__device__ __forceinline__ void mma16h(float* d, const unsigned* a,
                                       unsigned b0, unsigned b1) {
    asm volatile(
        "mma.sync.aligned.m16n8k16.row.col.f32.f16.f16.f32 "
        "{%0,%1,%2,%3}, {%4,%5,%6,%7}, {%8,%9}, {%0,%1,%2,%3};"
        : "+f"(d[0]), "+f"(d[1]), "+f"(d[2]), "+f"(d[3])
        : "r"(a[0]), "r"(a[1]), "r"(a[2]), "r"(a[3]), "r"(b0), "r"(b1));
}

__device__ __forceinline__ void ldsm4(unsigned* r, uint32_t a) {
    asm volatile("ldmatrix.sync.aligned.m8n8.x4.shared.b16 {%0,%1,%2,%3}, [%4];"
                 : "=r"(r[0]), "=r"(r[1]), "=r"(r[2]), "=r"(r[3]) : "r"(a));
}
__device__ __forceinline__ void ldsm4t(unsigned* r, uint32_t a) {
    asm volatile("ldmatrix.sync.aligned.m8n8.x4.trans.shared.b16 {%0,%1,%2,%3}, [%4];"
                 : "=r"(r[0]), "=r"(r[1]), "=r"(r[2]), "=r"(r[3]) : "r"(a));
}

#define CP_A16(dst, src) \
    asm volatile("cp.async.ca.shared.global [%0], [%1], 16;" :: "r"(dst), "l"(src) : "memory")
#define CP_A4(dst, src) \
    asm volatile("cp.async.ca.shared.global [%0], [%1], 4;" :: "r"(dst), "l"(src) : "memory")
#define CP_COMMIT() asm volatile("cp.async.commit_group;" ::: "memory")
#define CP_WAIT(n)  asm volatile("cp.async.wait_group %0;" :: "n"(n) : "memory")

// ======================= GEMM (fp16 mma + ldmatrix):  Y = X @ W^T =======================
// X: (M,K) row-major fp32, W: (N,K) row-major fp32 (converted to fp16 at STS).
// outmode 0: fp32 + bias.  outmode 1: fp16 of (scale*acc).
// Block 128x128, BK=32, 8 warps (warp tile 32x64). smem row stride 40 halves (80 B).
#define GKH 40

__global__ __launch_bounds__(256, 2)
void gemm_h(const float* __restrict__ X, const float* __restrict__ W,
            const float* __restrict__ bias, void* __restrict__ Yv,
            int outmode, float scale)
{
    __shared__ __half As[128 * GKH];
    __shared__ __half Bs[128 * GKH];

    const uint32_t abase = smem_u32(As);
    const uint32_t bbase = smem_u32(Bs);

    const int tid  = threadIdx.x;
    const int lane = tid & 31;
    const int wid  = tid >> 5;
    const int bm   = blockIdx.y * 128;
    const int bn   = blockIdx.x * 128;
    const int wm   = (wid & 3) * 32;
    const int wn   = (wid >> 2) * 64;
    const int g    = lane >> 2;
    const int t    = lane & 3;
    const int K    = D_MODEL;

    const int l7  = lane & 7;
    const int lb3 = (lane >> 3) & 1;
    const int lb4 = lane >> 4;

    // A-frag addr (per mt, per s): row = wm + mt*16 + l7 + (lane&8), k-chunk = lb4
    uint32_t aoff[2];
#pragma unroll
    for (int mt = 0; mt < 2; mt++)
        aoff[mt] = abase + (uint32_t)((wm + mt * 16 + l7 + (lane & 8)) * (GKH * 2)) + lb4 * 16;
    // B-frag addr (per np, per s): row = wn + np*16 + l7 + lb4*8, k-chunk = lb3
    const uint32_t boff0 = bbase + (uint32_t)((wn + l7 + lb4 * 8) * (GKH * 2)) + lb3 * 16;

    float acc[2][8][4];
#pragma unroll
    for (int mt = 0; mt < 2; mt++)
#pragma unroll
        for (int nt = 0; nt < 8; nt++)
#pragma unroll
            for (int e = 0; e < 4; e++) acc[mt][nt][e] = 0.0f;

    for (int k0 = 0; k0 < K; k0 += 32) {
        // ---- load fp32, cvt fp16, STS ----
#pragma unroll
        for (int i = 0; i < 4; i++) {
            int idx = tid + i * 256;          // 1024 float4 per operand
            int row = idx >> 3;
            int c4  = (idx & 7) * 4;
            float4 xv = *(const float4*)(X + (size_t)(bm + row) * K + k0 + c4);
            __half2 hx0 = __floats2half2_rn(xv.x, xv.y);
            __half2 hx1 = __floats2half2_rn(xv.z, xv.w);
            *(__half2*)((char*)As + row * (GKH * 2) + c4 * 2) = hx0;
            *(__half2*)((char*)As + row * (GKH * 2) + c4 * 2 + 4) = hx1;
            float4 wv = *(const float4*)(W + (size_t)(bn + row) * K + k0 + c4);
            __half2 hw0 = __floats2half2_rn(wv.x, wv.y);
            __half2 hw1 = __floats2half2_rn(wv.z, wv.w);
            *(__half2*)((char*)Bs + row * (GKH * 2) + c4 * 2) = hw0;
            *(__half2*)((char*)Bs + row * (GKH * 2) + c4 * 2 + 4) = hw1;
        }
        __syncthreads();

        // ---- 2 x k16 steps ----
#pragma unroll
        for (int s = 0; s < 2; s++) {
            unsigned a[2][4];
            ldsm4(a[0], aoff[0] + s * 32);
            ldsm4(a[1], aoff[1] + s * 32);
#pragma unroll
            for (int np = 0; np < 4; np++) {
                unsigned b4[4];
                ldsm4(b4, boff0 + np * 16 * (GKH * 2) + s * 32);
                mma16h(acc[0][2 * np],     a[0], b4[0], b4[1]);
                mma16h(acc[0][2 * np + 1], a[0], b4[2], b4[3]);
                mma16h(acc[1][2 * np],     a[1], b4[0], b4[1]);
                mma16h(acc[1][2 * np + 1], a[1], b4[2], b4[3]);
            }
        }
        __syncthreads();
    }

#pragma unroll
    for (int mt = 0; mt < 2; mt++)
#pragma unroll
        for (int hh = 0; hh < 2; hh++) {
            int row = bm + wm + mt * 16 + g + hh * 8;
#pragma unroll
            for (int nt = 0; nt < 8; nt++) {
                int col = bn + wn + nt * 8 + t * 2;
                float x = acc[mt][nt][hh * 2 + 0];
                float y = acc[mt][nt][hh * 2 + 1];
                if (outmode) {
                    __half2 h = __floats2half2_rn(x * scale, y * scale);
                    *(__half2*)((__half*)Yv + (size_t)row * D_MODEL + col) = h;
                } else {
                    float2 v;
                    v.x = x + (bias ? bias[col] : 0.0f);
                    v.y = y + (bias ? bias[col + 1] : 0.0f);
                    *(float2*)((float*)Yv + (size_t)row * D_MODEL + col) = v;
                }
            }
        }
}

// ======================= Flash attention: fp16 mma + ldmatrix (unchanged) =======================
#define HSTB 144                      // row stride bytes (72 halves)
#define QS_B   0                      // 128 rows
#define KS_B(b) (18432 + (b) * 9216)  // 64 rows each
#define VS_B(b) (36864 + (b) * 9216)
#define PS_B   55296                  // 128 rows
#define MK_B(b) (73728 + (b) * 256)   // 64 ints each
#define ATT_SMEM_BYTES (74240)

__global__ __launch_bounds__(256, 2)
void attn_h(const __half* __restrict__ Qb, const __half* __restrict__ Kb,
            const __half* __restrict__ Vb, const int* __restrict__ mask,
            float* __restrict__ ctx)
{
    extern __shared__ char sm[];
    const uint32_t sb = smem_u32(sm);

    const int tid  = threadIdx.x;
    const int lane = tid & 31;
    const int wid  = tid >> 5;
    const int g    = lane >> 2;
    const int t    = lane & 3;
    const int q0   = blockIdx.x * 128;
    const int hd   = blockIdx.y;
    const int b    = blockIdx.z;

    const __half* Qg = Qb + (size_t)(b * SEQ) * D_MODEL + hd * HDIM;
    const __half* Kg = Kb + (size_t)(b * SEQ) * D_MODEL + hd * HDIM;
    const __half* Vg = Vb + (size_t)(b * SEQ) * D_MODEL + hd * HDIM;
    const int*    Mg = mask + b * SEQ;

    int jr[2], jc[2];
#pragma unroll
    for (int i = 0; i < 2; i++) {
        int idx = tid + i * 256;
        jr[i] = idx >> 3;
        jc[i] = idx & 7;
    }

    auto issue_tile = [&](int buf, int kb) {
#pragma unroll
        for (int i = 0; i < 2; i++) {
            uint32_t doff = (uint32_t)(jr[i] * HSTB + jc[i] * 16);
            CP_A16(sb + KS_B(buf) + doff, Kg + (size_t)(kb + jr[i]) * D_MODEL + jc[i] * 8);
            CP_A16(sb + VS_B(buf) + doff, Vg + (size_t)(kb + jr[i]) * D_MODEL + jc[i] * 8);
        }
        if (tid < 64) CP_A4(sb + MK_B(buf) + tid * 4, Mg + kb + tid);
        CP_COMMIT();
    };

    issue_tile(0, 0);

#pragma unroll
    for (int i = 0; i < 4; i++) {
        int idx = tid + i * 256;
        int row = idx >> 3;
        int c8  = idx & 7;
        *(uint4*)(sm + QS_B + row * HSTB + c8 * 16) =
            *(const uint4*)(Qg + (size_t)(q0 + row) * D_MODEL + c8 * 8);
    }

    const int l7  = lane & 7;
    const int lb3 = (lane >> 3) & 1;
    const int lb4 = lane >> 4;
    const uint32_t qa = sb + QS_B + (uint32_t)((wid * 16 + l7 + (lane & 8)) * HSTB) + lb4 * 16;
    const uint32_t pa = sb + PS_B + (uint32_t)((wid * 16 + l7 + (lane & 8)) * HSTB) + lb4 * 16;
    const uint32_t koff = (uint32_t)((l7 + lb4 * 8) * HSTB) + lb3 * 16;
    const uint32_t voff = (uint32_t)((l7 + lb3 * 8) * HSTB) + lb4 * 16;

    float oacc[8][4];
#pragma unroll
    for (int dt = 0; dt < 8; dt++)
#pragma unroll
        for (int e = 0; e < 4; e++) oacc[dt][e] = 0.0f;
    float mrun[2] = {-1e30f, -1e30f};
    float lrun[2] = {0.0f, 0.0f};

    const int r = wid * 16 + g;
    const unsigned FULL = 0xffffffffu;
    const int NT = SEQ / 64;   // 32

    for (int ti = 0; ti < NT; ti++) {
        const int buf = ti & 1;
        if (ti + 1 < NT) { issue_tile(buf ^ 1, (ti + 1) * 64); CP_WAIT(1); }
        else             { CP_WAIT(0); }
        __syncthreads();

        const uint32_t kbase = sb + KS_B(buf) + koff;
        const uint32_t vbase = sb + VS_B(buf) + voff;
        const int*     Mk    = (const int*)(sm + MK_B(buf));

        float sacc[8][4];
#pragma unroll
        for (int nt = 0; nt < 8; nt++)
#pragma unroll
            for (int e = 0; e < 4; e++) sacc[nt][e] = 0.0f;

#pragma unroll
        for (int s = 0; s < 4; s++) {
            unsigned a[4];
            ldsm4(a, qa + s * 32);
#pragma unroll
            for (int np = 0; np < 4; np++) {
                unsigned kb4[4];
                ldsm4(kb4, kbase + np * 16 * HSTB + s * 32);
                mma16h(sacc[2 * np],     a, kb4[0], kb4[1]);
                mma16h(sacc[2 * np + 1], a, kb4[2], kb4[3]);
            }
        }

        float mx[2] = {-1e30f, -1e30f};
#pragma unroll
        for (int nt = 0; nt < 8; nt++) {
            float mk0 = Mk[nt * 8 + t * 2]     ? 0.0f : -1e30f;
            float mk1 = Mk[nt * 8 + t * 2 + 1] ? 0.0f : -1e30f;
            sacc[nt][0] += mk0; sacc[nt][1] += mk1;
            sacc[nt][2] += mk0; sacc[nt][3] += mk1;
            mx[0] = fmaxf(mx[0], fmaxf(sacc[nt][0], sacc[nt][1]));
            mx[1] = fmaxf(mx[1], fmaxf(sacc[nt][2], sacc[nt][3]));
        }
        float corr[2];
#pragma unroll
        for (int h2 = 0; h2 < 2; h2++) {
            mx[h2] = fmaxf(mx[h2], __shfl_xor_sync(FULL, mx[h2], 1));
            mx[h2] = fmaxf(mx[h2], __shfl_xor_sync(FULL, mx[h2], 2));
            float mn = fmaxf(mrun[h2], mx[h2]);
            corr[h2] = __expf(mrun[h2] - mn);
            mrun[h2] = mn;
        }
        float ls[2] = {0.0f, 0.0f};
#pragma unroll
        for (int nt = 0; nt < 8; nt++) {
            sacc[nt][0] = __expf(sacc[nt][0] - mrun[0]);
            sacc[nt][1] = __expf(sacc[nt][1] - mrun[0]);
            sacc[nt][2] = __expf(sacc[nt][2] - mrun[1]);
            sacc[nt][3] = __expf(sacc[nt][3] - mrun[1]);
            ls[0] += sacc[nt][0] + sacc[nt][1];
            ls[1] += sacc[nt][2] + sacc[nt][3];
        }
#pragma unroll
        for (int h2 = 0; h2 < 2; h2++) {
            ls[h2] += __shfl_xor_sync(FULL, ls[h2], 1);
            ls[h2] += __shfl_xor_sync(FULL, ls[h2], 2);
            lrun[h2] = lrun[h2] * corr[h2] + ls[h2];
        }
#pragma unroll
        for (int dt = 0; dt < 8; dt++) {
            oacc[dt][0] *= corr[0]; oacc[dt][1] *= corr[0];
            oacc[dt][2] *= corr[1]; oacc[dt][3] *= corr[1];
        }

#pragma unroll
        for (int nt = 0; nt < 8; nt++) {
            int cb = (nt * 8 + t * 2) * 2;
            *(__half2*)(sm + PS_B + r * HSTB + cb) =
                __floats2half2_rn(sacc[nt][0], sacc[nt][1]);
            *(__half2*)(sm + PS_B + (r + 8) * HSTB + cb) =
                __floats2half2_rn(sacc[nt][2], sacc[nt][3]);
        }
        __syncwarp();

#pragma unroll
        for (int s = 0; s < 4; s++) {
            unsigned p4[4];
            ldsm4(p4, pa + s * 32);
#pragma unroll
            for (int dp = 0; dp < 4; dp++) {
                unsigned vb4[4];
                ldsm4t(vb4, vbase + s * 16 * HSTB + dp * 32);
                mma16h(oacc[2 * dp],     p4, vb4[0], vb4[1]);
                mma16h(oacc[2 * dp + 1], p4, vb4[2], vb4[3]);
            }
        }
        __syncthreads();
    }

    float inv[2];
    inv[0] = (mrun[0] > -9e29f) ? (1.0f / lrun[0]) : 0.0f;
    inv[1] = (mrun[1] > -9e29f) ? (1.0f / lrun[1]) : 0.0f;
#pragma unroll
    for (int h2 = 0; h2 < 2; h2++) {
        int row = q0 + r + h2 * 8;
        float* dst = ctx + (size_t)(b * SEQ + row) * D_MODEL + hd * HDIM;
#pragma unroll
        for (int dt = 0; dt < 8; dt++) {
            float2 v;
            v.x = oacc[dt][h2 * 2 + 0] * inv[h2];
            v.y = oacc[dt][h2 * 2 + 1] * inv[h2];
            *(float2*)(dst + dt * 8 + t * 2) = v;
        }
    }
}

// ======================= launch =======================
extern "C" void kernel_launch(void* const* d_in, const int* in_sizes, int n_in,
                              void* d_out, int out_size)
{
    const float* q   = (const float*)d_in[0];
    const float* k   = (const float*)d_in[1];
    const float* v   = (const float*)d_in[2];
    const int*   msk = (const int*)  d_in[3];
    const float* Wq  = (const float*)d_in[4];
    const float* Wk  = (const float*)d_in[5];
    const float* Wv  = (const float*)d_in[6];
    const float* Wo  = (const float*)d_in[7];
    const float* bo  = (const float*)d_in[8];
    float* out = (float*)d_out;

    __half *gq, *gk, *gv;
    float  *gc;
    cudaGetSymbolAddress((void**)&gq, g_qh);
    cudaGetSymbolAddress((void**)&gk, g_kh);
    cudaGetSymbolAddress((void**)&gv, g_vh);
    cudaGetSymbolAddress((void**)&gc, g_c);

    cudaFuncSetAttribute(attn_h,
                         cudaFuncAttributeMaxDynamicSharedMemorySize, ATT_SMEM_BYTES);

    dim3 gg(D_MODEL / 128, MTOK / 128);   // (8, 32)

    gemm_h<<<gg, 256>>>(q, Wq, nullptr, gq, 1, 0.125f);  // Q -> fp16, pre-scaled
    gemm_h<<<gg, 256>>>(k, Wk, nullptr, gk, 1, 1.0f);    // K -> fp16
    gemm_h<<<gg, 256>>>(v, Wv, nullptr, gv, 1, 1.0f);    // V -> fp16

    dim3 ag(SEQ / 128, NHEAD, BATCH);     // (16, 16, 2)
    attn_h<<<ag, 256, ATT_SMEM_BYTES>>>(gq, gk, gv, msk, gc);

    gemm_h<<<gg, 256>>>(gc, Wo, bo, out, 0, 1.0f);       // O proj fp32 + bias
}

// round 9
// speedup vs baseline: 2.8597x; 1.1076x over previous
#include <cuda_runtime.h>
#include <cuda_fp16.h>
#include <cstdint>
#include <math.h>

#define D_MODEL 1024
#define NHEAD   16
#define HDIM    64
#define BATCH   2
#define SEQ     2048
#define MTOK    (BATCH * SEQ)   // 4096

// -------- scratch (static device globals; no allocation allowed) --------
__device__ __half g_xq[MTOK * D_MODEL];       // fp16 query input
__device__ __half g_xk[MTOK * D_MODEL];       // fp16 key input
__device__ __half g_xv[MTOK * D_MODEL];       // fp16 value input
__device__ __half g_wq[D_MODEL * D_MODEL];    // fp16 Wq * 0.125
__device__ __half g_wk[D_MODEL * D_MODEL];    // fp16 Wk
__device__ __half g_wv[D_MODEL * D_MODEL];    // fp16 Wv
__device__ __half g_wo[D_MODEL * D_MODEL];    // fp16 Wo
__device__ __half g_qh[MTOK * D_MODEL];       // fp16 Q (pre-scaled)
__device__ __half g_kh[MTOK * D_MODEL];       // fp16 K
__device__ __half g_vh[MTOK * D_MODEL];       // fp16 V
__device__ __half g_ch[MTOK * D_MODEL];       // fp16 ctx

// ======================= helpers =======================
__device__ __forceinline__ uint32_t smem_u32(const void* p) {
    uint32_t a;
    asm("{ .reg .u64 t; cvta.to.shared.u64 t, %1; cvt.u32.u64 %0, t; }"
        : "=r"(a) : "l"(p));
    return a;
}

__device__ __forceinline__ void mma16h(float* d, const unsigned* a,
                                       unsigned b0, unsigned b1) {
    asm volatile(
        "mma.sync.aligned.m16n8k16.row.col.f32.f16.f16.f32 "
        "{%0,%1,%2,%3}, {%4,%5,%6,%7}, {%8,%9}, {%0,%1,%2,%3};"
        : "+f"(d[0]), "+f"(d[1]), "+f"(d[2]), "+f"(d[3])
        : "r"(a[0]), "r"(a[1]), "r"(a[2]), "r"(a[3]), "r"(b0), "r"(b1));
}

__device__ __forceinline__ void ldsm4(unsigned* r, uint32_t a) {
    asm volatile("ldmatrix.sync.aligned.m8n8.x4.shared.b16 {%0,%1,%2,%3}, [%4];"
                 : "=r"(r[0]), "=r"(r[1]), "=r"(r[2]), "=r"(r[3]) : "r"(a));
}
__device__ __forceinline__ void ldsm4t(unsigned* r, uint32_t a) {
    asm volatile("ldmatrix.sync.aligned.m8n8.x4.trans.shared.b16 {%0,%1,%2,%3}, [%4];"
                 : "=r"(r[0]), "=r"(r[1]), "=r"(r[2]), "=r"(r[3]) : "r"(a));
}

#define CP_A16(dst, src) \
    asm volatile("cp.async.ca.shared.global [%0], [%1], 16;" :: "r"(dst), "l"(src) : "memory")
#define CP_A4(dst, src) \
    asm volatile("cp.async.ca.shared.global [%0], [%1], 4;" :: "r"(dst), "l"(src) : "memory")
#define CP_COMMIT() asm volatile("cp.async.commit_group;" ::: "memory")
#define CP_WAIT(n)  asm volatile("cp.async.wait_group %0;" :: "n"(n) : "memory")

// ======================= pre-convert: fp32 -> fp16 =======================
// blockIdx.y selects tensor: 0-2 inputs (4M elems), 3-6 weights (1M elems).
__global__ __launch_bounds__(256)
void cvt_all(const float* __restrict__ q, const float* __restrict__ k,
             const float* __restrict__ v, const float* __restrict__ wq,
             const float* __restrict__ wk, const float* __restrict__ wv,
             const float* __restrict__ wo,
             __half* __restrict__ xq, __half* __restrict__ xk,
             __half* __restrict__ xv, __half* __restrict__ hwq,
             __half* __restrict__ hwk, __half* __restrict__ hwv,
             __half* __restrict__ hwo)
{
    const float* src; __half* dst; int n; float sc = 1.0f;
    switch (blockIdx.y) {
        case 0: src = q;  dst = xq;  n = MTOK * D_MODEL; break;
        case 1: src = k;  dst = xk;  n = MTOK * D_MODEL; break;
        case 2: src = v;  dst = xv;  n = MTOK * D_MODEL; break;
        case 3: src = wq; dst = hwq; n = D_MODEL * D_MODEL; sc = 0.125f; break;
        case 4: src = wk; dst = hwk; n = D_MODEL * D_MODEL; break;
        case 5: src = wv; dst = hwv; n = D_MODEL * D_MODEL; break;
        default: src = wo; dst = hwo; n = D_MODEL * D_MODEL; break;
    }
    int i = (blockIdx.x * 256 + threadIdx.x) * 4;
    if (i < n) {
        float4 f = *(const float4*)(src + i);
        *(__half2*)(dst + i)     = __floats2half2_rn(f.x * sc, f.y * sc);
        *(__half2*)(dst + i + 2) = __floats2half2_rn(f.z * sc, f.w * sc);
    }
}

// ======================= GEMM (pure fp16, cp.async 3-stage, BK=64) =======================
// X: (M,K) row-major fp16, W: (N,K) row-major fp16.
// outmode 0: fp32 + bias.  outmode 1: fp16.
#define G2ST   144                 // row stride bytes (72 halves; conflict-free LDSM)
#define G2_OP  (128 * G2ST)        // 18432 per operand per stage
#define G2_STAGE (2 * G2_OP)       // 36864
#define G2_SMEM  (3 * G2_STAGE)    // 110592

__global__ __launch_bounds__(256, 2)
void gemm_h2(const __half* __restrict__ X, const __half* __restrict__ W,
             const float* __restrict__ bias, void* __restrict__ Yv, int outmode)
{
    extern __shared__ char smem[];
    const uint32_t sb = smem_u32(smem);

    const int tid  = threadIdx.x;
    const int lane = tid & 31;
    const int wid  = tid >> 5;
    const int bm   = blockIdx.y * 128;
    const int bn   = blockIdx.x * 128;
    const int wm   = (wid & 3) * 32;
    const int wn   = (wid >> 2) * 64;
    const int g    = lane >> 2;
    const int t    = lane & 3;
    const int K    = D_MODEL;

    const int l7  = lane & 7;
    const int lb3 = (lane >> 3) & 1;
    const int lb4 = lane >> 4;

    // load coords: 128 rows x 8 16B-chunks per operand = 1024, 4/thread
    int lrow[4], lc[4];
#pragma unroll
    for (int i = 0; i < 4; i++) {
        int idx = tid + i * 256;
        lrow[i] = idx >> 3;
        lc[i]   = idx & 7;
    }

    auto issue = [&](int s) {
        uint32_t st = sb + (uint32_t)(s % 3) * G2_STAGE;
        int k0 = s * 64;
#pragma unroll
        for (int i = 0; i < 4; i++) {
            uint32_t doff = (uint32_t)(lrow[i] * G2ST + lc[i] * 16);
            CP_A16(st + doff,         X + (size_t)(bm + lrow[i]) * K + k0 + lc[i] * 8);
            CP_A16(st + G2_OP + doff, W + (size_t)(bn + lrow[i]) * K + k0 + lc[i] * 8);
        }
        CP_COMMIT();
    };

    // fragment offsets (within a stage)
    uint32_t aoffb[2];
#pragma unroll
    for (int mt = 0; mt < 2; mt++)
        aoffb[mt] = (uint32_t)((wm + mt * 16 + l7 + (lane & 8)) * G2ST) + lb4 * 16;
    const uint32_t boffb = (uint32_t)((wn + l7 + lb4 * 8) * G2ST) + lb3 * 16;

    float acc[2][8][4];
#pragma unroll
    for (int mt = 0; mt < 2; mt++)
#pragma unroll
        for (int nt = 0; nt < 8; nt++)
#pragma unroll
            for (int e = 0; e < 4; e++) acc[mt][nt][e] = 0.0f;

    const int NS = K / 64;   // 16
    issue(0); issue(1);

    for (int s = 0; s < NS; s++) {
        if (s + 1 < NS) CP_WAIT(1);
        else            CP_WAIT(0);
        __syncthreads();
        if (s + 2 < NS) issue(s + 2);

        uint32_t ab = sb + (uint32_t)(s % 3) * G2_STAGE;
        uint32_t bb = ab + G2_OP;
#pragma unroll
        for (int s16 = 0; s16 < 4; s16++) {
            unsigned a[2][4];
            ldsm4(a[0], ab + aoffb[0] + s16 * 32);
            ldsm4(a[1], ab + aoffb[1] + s16 * 32);
#pragma unroll
            for (int np = 0; np < 4; np++) {
                unsigned b4[4];
                ldsm4(b4, bb + boffb + np * 16 * G2ST + s16 * 32);
                mma16h(acc[0][2 * np],     a[0], b4[0], b4[1]);
                mma16h(acc[0][2 * np + 1], a[0], b4[2], b4[3]);
                mma16h(acc[1][2 * np],     a[1], b4[0], b4[1]);
                mma16h(acc[1][2 * np + 1], a[1], b4[2], b4[3]);
            }
        }
    }

#pragma unroll
    for (int mt = 0; mt < 2; mt++)
#pragma unroll
        for (int hh = 0; hh < 2; hh++) {
            int row = bm + wm + mt * 16 + g + hh * 8;
#pragma unroll
            for (int nt = 0; nt < 8; nt++) {
                int col = bn + wn + nt * 8 + t * 2;
                float x = acc[mt][nt][hh * 2 + 0];
                float y = acc[mt][nt][hh * 2 + 1];
                if (outmode) {
                    *(__half2*)((__half*)Yv + (size_t)row * D_MODEL + col) =
                        __floats2half2_rn(x, y);
                } else {
                    float2 v;
                    v.x = x + bias[col];
                    v.y = y + bias[col + 1];
                    *(float2*)((float*)Yv + (size_t)row * D_MODEL + col) = v;
                }
            }
        }
}

// ======================= Flash attention: fp16 mma + ldmatrix =======================
#define HSTB 144                      // row stride bytes (72 halves)
#define QS_B   0                      // 128 rows
#define KS_B(b) (18432 + (b) * 9216)  // 64 rows each
#define VS_B(b) (36864 + (b) * 9216)
#define PS_B   55296                  // 128 rows
#define MK_B(b) (73728 + (b) * 256)   // 64 ints each
#define ATT_SMEM_BYTES (74240)

__global__ __launch_bounds__(256, 2)
void attn_h(const __half* __restrict__ Qb, const __half* __restrict__ Kb,
            const __half* __restrict__ Vb, const int* __restrict__ mask,
            __half* __restrict__ ctx)
{
    extern __shared__ char sm[];
    const uint32_t sb = smem_u32(sm);

    const int tid  = threadIdx.x;
    const int lane = tid & 31;
    const int wid  = tid >> 5;
    const int g    = lane >> 2;
    const int t    = lane & 3;
    const int q0   = blockIdx.x * 128;
    const int hd   = blockIdx.y;
    const int b    = blockIdx.z;

    const __half* Qg = Qb + (size_t)(b * SEQ) * D_MODEL + hd * HDIM;
    const __half* Kg = Kb + (size_t)(b * SEQ) * D_MODEL + hd * HDIM;
    const __half* Vg = Vb + (size_t)(b * SEQ) * D_MODEL + hd * HDIM;
    const int*    Mg = mask + b * SEQ;

    int jr[2], jc[2];
#pragma unroll
    for (int i = 0; i < 2; i++) {
        int idx = tid + i * 256;
        jr[i] = idx >> 3;
        jc[i] = idx & 7;
    }

    auto issue_tile = [&](int buf, int kb) {
#pragma unroll
        for (int i = 0; i < 2; i++) {
            uint32_t doff = (uint32_t)(jr[i] * HSTB + jc[i] * 16);
            CP_A16(sb + KS_B(buf) + doff, Kg + (size_t)(kb + jr[i]) * D_MODEL + jc[i] * 8);
            CP_A16(sb + VS_B(buf) + doff, Vg + (size_t)(kb + jr[i]) * D_MODEL + jc[i] * 8);
        }
        if (tid < 64) CP_A4(sb + MK_B(buf) + tid * 4, Mg + kb + tid);
        CP_COMMIT();
    };

    issue_tile(0, 0);

#pragma unroll
    for (int i = 0; i < 4; i++) {
        int idx = tid + i * 256;
        int row = idx >> 3;
        int c8  = idx & 7;
        *(uint4*)(sm + QS_B + row * HSTB + c8 * 16) =
            *(const uint4*)(Qg + (size_t)(q0 + row) * D_MODEL + c8 * 8);
    }

    const int l7  = lane & 7;
    const int lb3 = (lane >> 3) & 1;
    const int lb4 = lane >> 4;
    const uint32_t qa = sb + QS_B + (uint32_t)((wid * 16 + l7 + (lane & 8)) * HSTB) + lb4 * 16;
    const uint32_t pa = sb + PS_B + (uint32_t)((wid * 16 + l7 + (lane & 8)) * HSTB) + lb4 * 16;
    const uint32_t koff = (uint32_t)((l7 + lb4 * 8) * HSTB) + lb3 * 16;
    const uint32_t voff = (uint32_t)((l7 + lb3 * 8) * HSTB) + lb4 * 16;

    float oacc[8][4];
#pragma unroll
    for (int dt = 0; dt < 8; dt++)
#pragma unroll
        for (int e = 0; e < 4; e++) oacc[dt][e] = 0.0f;
    float mrun[2] = {-1e30f, -1e30f};
    float lrun[2] = {0.0f, 0.0f};

    const int r = wid * 16 + g;
    const unsigned FULL = 0xffffffffu;
    const int NT = SEQ / 64;   // 32

    for (int ti = 0; ti < NT; ti++) {
        const int buf = ti & 1;
        if (ti + 1 < NT) { issue_tile(buf ^ 1, (ti + 1) * 64); CP_WAIT(1); }
        else             { CP_WAIT(0); }
        __syncthreads();

        const uint32_t kbase = sb + KS_B(buf) + koff;
        const uint32_t vbase = sb + VS_B(buf) + voff;
        const int*     Mk    = (const int*)(sm + MK_B(buf));

        float sacc[8][4];
#pragma unroll
        for (int nt = 0; nt < 8; nt++)
#pragma unroll
            for (int e = 0; e < 4; e++) sacc[nt][e] = 0.0f;

#pragma unroll
        for (int s = 0; s < 4; s++) {
            unsigned a[4];
            ldsm4(a, qa + s * 32);
#pragma unroll
            for (int np = 0; np < 4; np++) {
                unsigned kb4[4];
                ldsm4(kb4, kbase + np * 16 * HSTB + s * 32);
                mma16h(sacc[2 * np],     a, kb4[0], kb4[1]);
                mma16h(sacc[2 * np + 1], a, kb4[2], kb4[3]);
            }
        }

        float mx[2] = {-1e30f, -1e30f};
#pragma unroll
        for (int nt = 0; nt < 8; nt++) {
            float mk0 = Mk[nt * 8 + t * 2]     ? 0.0f : -1e30f;
            float mk1 = Mk[nt * 8 + t * 2 + 1] ? 0.0f : -1e30f;
            sacc[nt][0] += mk0; sacc[nt][1] += mk1;
            sacc[nt][2] += mk0; sacc[nt][3] += mk1;
            mx[0] = fmaxf(mx[0], fmaxf(sacc[nt][0], sacc[nt][1]));
            mx[1] = fmaxf(mx[1], fmaxf(sacc[nt][2], sacc[nt][3]));
        }
        float corr[2];
#pragma unroll
        for (int h2 = 0; h2 < 2; h2++) {
            mx[h2] = fmaxf(mx[h2], __shfl_xor_sync(FULL, mx[h2], 1));
            mx[h2] = fmaxf(mx[h2], __shfl_xor_sync(FULL, mx[h2], 2));
            float mn = fmaxf(mrun[h2], mx[h2]);
            corr[h2] = __expf(mrun[h2] - mn);
            mrun[h2] = mn;
        }
        float ls[2] = {0.0f, 0.0f};
#pragma unroll
        for (int nt = 0; nt < 8; nt++) {
            sacc[nt][0] = __expf(sacc[nt][0] - mrun[0]);
            sacc[nt][1] = __expf(sacc[nt][1] - mrun[0]);
            sacc[nt][2] = __expf(sacc[nt][2] - mrun[1]);
            sacc[nt][3] = __expf(sacc[nt][3] - mrun[1]);
            ls[0] += sacc[nt][0] + sacc[nt][1];
            ls[1] += sacc[nt][2] + sacc[nt][3];
        }
#pragma unroll
        for (int h2 = 0; h2 < 2; h2++) {
            ls[h2] += __shfl_xor_sync(FULL, ls[h2], 1);
            ls[h2] += __shfl_xor_sync(FULL, ls[h2], 2);
            lrun[h2] = lrun[h2] * corr[h2] + ls[h2];
        }
#pragma unroll
        for (int dt = 0; dt < 8; dt++) {
            oacc[dt][0] *= corr[0]; oacc[dt][1] *= corr[0];
            oacc[dt][2] *= corr[1]; oacc[dt][3] *= corr[1];
        }

#pragma unroll
        for (int nt = 0; nt < 8; nt++) {
            int cb = (nt * 8 + t * 2) * 2;
            *(__half2*)(sm + PS_B + r * HSTB + cb) =
                __floats2half2_rn(sacc[nt][0], sacc[nt][1]);
            *(__half2*)(sm + PS_B + (r + 8) * HSTB + cb) =
                __floats2half2_rn(sacc[nt][2], sacc[nt][3]);
        }
        __syncwarp();

#pragma unroll
        for (int s = 0; s < 4; s++) {
            unsigned p4[4];
            ldsm4(p4, pa + s * 32);
#pragma unroll
            for (int dp = 0; dp < 4; dp++) {
                unsigned vb4[4];
                ldsm4t(vb4, vbase + s * 16 * HSTB + dp * 32);
                mma16h(oacc[2 * dp],     p4, vb4[0], vb4[1]);
                mma16h(oacc[2 * dp + 1], p4, vb4[2], vb4[3]);
            }
        }
        __syncthreads();
    }

    float inv[2];
    inv[0] = (mrun[0] > -9e29f) ? (1.0f / lrun[0]) : 0.0f;
    inv[1] = (mrun[1] > -9e29f) ? (1.0f / lrun[1]) : 0.0f;
#pragma unroll
    for (int h2 = 0; h2 < 2; h2++) {
        int row = q0 + r + h2 * 8;
        __half* dst = ctx + (size_t)(b * SEQ + row) * D_MODEL + hd * HDIM;
#pragma unroll
        for (int dt = 0; dt < 8; dt++) {
            *(__half2*)(dst + dt * 8 + t * 2) =
                __floats2half2_rn(oacc[dt][h2 * 2 + 0] * inv[h2],
                                  oacc[dt][h2 * 2 + 1] * inv[h2]);
        }
    }
}

// ======================= launch =======================
extern "C" void kernel_launch(void* const* d_in, const int* in_sizes, int n_in,
                              void* d_out, int out_size)
{
    const float* q   = (const float*)d_in[0];
    const float* k   = (const float*)d_in[1];
    const float* v   = (const float*)d_in[2];
    const int*   msk = (const int*)  d_in[3];
    const float* Wq  = (const float*)d_in[4];
    const float* Wk  = (const float*)d_in[5];
    const float* Wv  = (const float*)d_in[6];
    const float* Wo  = (const float*)d_in[7];
    const float* bo  = (const float*)d_in[8];
    float* out = (float*)d_out;

    __half *xq, *xk, *xv, *wq, *wk, *wv, *wo, *gq, *gk, *gv, *gc;
    cudaGetSymbolAddress((void**)&xq, g_xq);
    cudaGetSymbolAddress((void**)&xk, g_xk);
    cudaGetSymbolAddress((void**)&xv, g_xv);
    cudaGetSymbolAddress((void**)&wq, g_wq);
    cudaGetSymbolAddress((void**)&wk, g_wk);
    cudaGetSymbolAddress((void**)&wv, g_wv);
    cudaGetSymbolAddress((void**)&wo, g_wo);
    cudaGetSymbolAddress((void**)&gq, g_qh);
    cudaGetSymbolAddress((void**)&gk, g_kh);
    cudaGetSymbolAddress((void**)&gv, g_vh);
    cudaGetSymbolAddress((void**)&gc, g_ch);

    cudaFuncSetAttribute(gemm_h2,
                         cudaFuncAttributeMaxDynamicSharedMemorySize, G2_SMEM);
    cudaFuncSetAttribute(attn_h,
                         cudaFuncAttributeMaxDynamicSharedMemorySize, ATT_SMEM_BYTES);

    // pre-convert everything to fp16 (Wq scaled by 0.125)
    cvt_all<<<dim3(MTOK * D_MODEL / 4 / 256, 7), 256>>>(
        q, k, v, Wq, Wk, Wv, Wo, xq, xk, xv, wq, wk, wv, wo);

    dim3 gg(D_MODEL / 128, MTOK / 128);   // (8, 32)

    gemm_h2<<<gg, 256, G2_SMEM>>>(xq, wq, nullptr, gq, 1);  // Q (pre-scaled via Wq)
    gemm_h2<<<gg, 256, G2_SMEM>>>(xk, wk, nullptr, gk, 1);  // K
    gemm_h2<<<gg, 256, G2_SMEM>>>(xv, wv, nullptr, gv, 1);  // V

    dim3 ag(SEQ / 128, NHEAD, BATCH);     // (16, 16, 2)
    attn_h<<<ag, 256, ATT_SMEM_BYTES>>>(gq, gk, gv, msk, gc);

    gemm_h2<<<gg, 256, G2_SMEM>>>(gc, wo, bo, out, 0);      // O proj fp32 + bias
}